// round 1
// baseline (speedup 1.0000x reference)
#include <cuda_runtime.h>
#include <math.h>
#include <float.h>

#define NB 2
#define NS 1024
#define ND 512
#define NTOK (NB*NS)
#define NNEUR 4096
#define NCAND 288
#define MPC 32
#define GRID_C 16
#define NHEAD 8
#define DHEAD 64

// ---------------- device scratch (static, no allocation) ----------------
__device__ float g_Q[NTOK*ND];
__device__ float g_K[NTOK*ND];
__device__ float g_V[NTOK*ND];
__device__ float g_AO[NTOK*ND];
__device__ float g_posbuf[NTOK*2];

// ---------------- helpers ----------------
__device__ __forceinline__ unsigned f2u(float f){
    unsigned u = __float_as_uint(f);
    return (u & 0x80000000u) ? ~u : (u | 0x80000000u);
}
__device__ __forceinline__ float u2f(unsigned u){
    u = (u & 0x80000000u) ? (u & 0x7FFFFFFFu) : ~u;
    return __uint_as_float(u);
}
// eg = exp(gate) - 1, gate = raw>0 ? raw : 1e-8*exp(raw)   (matches reference fp32)
__device__ __forceinline__ float egf(float score, float tau){
    float raw = score - tau;
    float gate = raw > 0.f ? raw : 1e-8f * expf(raw);
    return expf(gate) - 1.0f;
}

struct TokSmem {
    float x[ND];
    int   cand[NCAND];
    float act[NCAND];
    float egA[NCAND];
    float egB[NCAND];
    float kc1[NCAND];
    float kc2[NCAND];
    int   klist[NCAND];
    unsigned mask[9];
    unsigned long long redu[8];
    float redf[3][8];
    int   wcnt[8];
    float bc[2];
    int   icnt;
};

// 32nd-largest (counting duplicates) of eg[0..287], block-cooperative.
// Also returns the global max via *out_max. Exactly mirrors top_k semantics.
__device__ float topk32(const float* eg, TokSmem* sm, int tid, float* out_max){
    if (tid < 9) sm->mask[tid] = 0u;
    __syncthreads();
    float tv = 0.f, mx = 0.f;
    for (int k = 0; k < 32; k++){
        float bv = -FLT_MAX; int bi = 0;
        for (int i = tid; i < NCAND; i += 256){
            if ((sm->mask[i >> 5] >> (i & 31)) & 1u) continue;
            float v = eg[i];
            if (v > bv){ bv = v; bi = i; }
        }
        unsigned long long key = (((unsigned long long)f2u(bv)) << 32) | (unsigned)bi;
        #pragma unroll
        for (int o = 16; o; o >>= 1){
            unsigned long long other = __shfl_xor_sync(0xffffffffu, key, o);
            if (other > key) key = other;
        }
        if ((tid & 31) == 0) sm->redu[tid >> 5] = key;
        __syncthreads();
        if (tid < 32){
            unsigned long long kk = (tid < 8) ? sm->redu[tid] : 0ull;
            #pragma unroll
            for (int o = 4; o; o >>= 1){
                unsigned long long other = __shfl_xor_sync(0xffffffffu, kk, o);
                if (other > kk) kk = other;
            }
            if (tid == 0) sm->redu[0] = kk;
        }
        __syncthreads();
        unsigned long long best = sm->redu[0];
        int idx = (int)(best & 0xffffffffull);
        float val = u2f((unsigned)(best >> 32));
        if (tid == 0) sm->mask[idx >> 5] |= (1u << (idx & 31));
        if (k == 0) mx = val;
        tv = val;
        __syncthreads();
    }
    *out_max = mx;
    return tv;
}

// fill candidate indices for one set
__device__ __forceinline__ void fill_cands(TokSmem* sm, int tid, float px, float py,
                                           float pm0, float pm1, float pr0, float pr1,
                                           const int* __restrict__ cmap){
    float nx = (px - pm0) / pr0, ny = (py - pm1) / pr1;
    int cx = min(max((int)(nx * GRID_C), 0), GRID_C - 1);
    int cy = min(max((int)(ny * GRID_C), 0), GRID_C - 1);
    for (int i = tid; i < NCAND; i += 256){
        int c = i / MPC;
        int rx = min(max(cx + c / 3 - 1, 0), GRID_C - 1);
        int ry = min(max(cy + c % 3 - 1, 0), GRID_C - 1);
        sm->cand[i] = cmap[(rx * GRID_C + ry) * MPC + (i % MPC)];
    }
}

// dot products for all candidates of one set: warp per candidate, interleaved
__device__ __forceinline__ void cand_dots(TokSmem* sm, int tid, const float* __restrict__ neurons){
    int w = tid >> 5, ln = tid & 31;
    for (int i = w; i < NCAND; i += 8){
        int idx = sm->cand[i]; if (idx < 0) idx = 0;
        const float* row = neurons + (size_t)idx * ND;
        float s = 0.f;
        #pragma unroll
        for (int e = 0; e < ND / 32; e++) s += row[ln + e * 32] * sm->x[ln + e * 32];
        #pragma unroll
        for (int o = 16; o; o >>= 1) s += __shfl_xor_sync(0xffffffffu, s, o);
        if (ln == 0) sm->act[i] = s;
    }
}

__global__ __launch_bounds__(256)
void token_kernel(const float* __restrict__ x,
                  const float* __restrict__ qk_pos, const float* __restrict__ v_pos,
                  const float* __restrict__ tau_Q, const float* __restrict__ tau_K,
                  const float* __restrict__ tau_V,
                  const float* __restrict__ qk_neurons, const float* __restrict__ v_neurons,
                  const float* __restrict__ npos_qk, const float* __restrict__ npos_v,
                  const int* __restrict__ cm_qk, const int* __restrict__ cm_v,
                  const float* __restrict__ pos_min, const float* __restrict__ pos_range)
{
    __shared__ TokSmem sm;
    int token = blockIdx.x;
    int tid = threadIdx.x;

    for (int i = tid; i < ND; i += 256) sm.x[i] = x[(size_t)token * ND + i];

    float pm0 = pos_min[0], pm1 = pos_min[1];
    float pr0 = pos_range[0], pr1 = pos_range[1];

    // ================= QK set (gates Q and K) =================
    {
        float px = qk_pos[token * 2 + 0], py = qk_pos[token * 2 + 1];
        fill_cands(&sm, tid, px, py, pm0, pm1, pr0, pr1, cm_qk);
        __syncthreads();
        cand_dots(&sm, tid, qk_neurons);
        float tq = tau_Q[token], tk = tau_K[token];
        __syncthreads();
        for (int i = tid; i < NCAND; i += 256){
            float a = sm.act[i];
            float sc = (sm.cand[i] >= 0) ? a : -1e9f;
            sm.egA[i] = egf(sc, tq);
            sm.egB[i] = egf(sc, tk);
        }
        __syncthreads();
        float mxQ, mxK;
        float tvQ = topk32(sm.egA, &sm, tid, &mxQ);
        float tvK = topk32(sm.egB, &sm, tid, &mxK);

        if (tid == 0) sm.icnt = 0;
        __syncthreads();
        float sQ = 0.f, sK = 0.f, sQpd = 0.f;
        for (int r = 0; r < 2; r++){
            int i = r * 256 + tid;
            bool inb = (i < NCAND);
            float a = 0.f, wQ = 0.f, wK = 0.f; int c = -1;
            bool keep = false;
            if (inb){
                c = sm.cand[i];
                a = sm.act[i];
                float eQ = sm.egA[i], eK = sm.egB[i];
                float kq = (eQ >= tvQ) ? eQ : 0.f;
                float kk = (eK >= tvK) ? eK : 0.f;
                if (c >= 0){
                    wQ = kq; wK = kk;
                    sQ += wQ; sK += wK;
                    if (wQ > 0.f){
                        float dx = px - npos_qk[c * 2], dy = py - npos_qk[c * 2 + 1];
                        sQpd += wQ * (dx * dx + dy * dy);
                    }
                    keep = (wQ != 0.f) || (wK != 0.f);
                }
            }
            unsigned bal = __ballot_sync(0xffffffffu, keep);
            int wlt = __popc(bal & ((1u << (tid & 31)) - 1u));
            if ((tid & 31) == 0) sm.wcnt[tid >> 5] = __popc(bal);
            __syncthreads();
            if (tid == 0){
                int base = sm.icnt;
                for (int w2 = 0; w2 < 8; w2++){ int t = sm.wcnt[w2]; sm.wcnt[w2] = base; base += t; }
                sm.icnt = base;
            }
            __syncthreads();
            if (keep){
                int p = sm.wcnt[tid >> 5] + wlt;
                sm.klist[p] = c;
                sm.kc1[p] = a * wQ;
                sm.kc2[p] = a * wK;
            }
            __syncthreads();
        }
        #pragma unroll
        for (int o = 16; o; o >>= 1){
            sQ   += __shfl_xor_sync(0xffffffffu, sQ, o);
            sK   += __shfl_xor_sync(0xffffffffu, sK, o);
            sQpd += __shfl_xor_sync(0xffffffffu, sQpd, o);
        }
        if ((tid & 31) == 0){
            sm.redf[0][tid >> 5] = sQ; sm.redf[1][tid >> 5] = sK; sm.redf[2][tid >> 5] = sQpd;
        }
        __syncthreads();
        if (tid == 0){
            float a0 = 0.f, a1 = 0.f, a2 = 0.f;
            for (int w2 = 0; w2 < 8; w2++){ a0 += sm.redf[0][w2]; a1 += sm.redf[1][w2]; a2 += sm.redf[2][w2]; }
            float scQ = tanhf(mxQ) / (a0 + 1e-8f);
            float scK = tanhf(mxK) / (a1 + 1e-8f);
            sm.bc[0] = scQ; sm.bc[1] = scK;
            g_posbuf[token] = scQ * a2;
        }
        __syncthreads();
        {
            int nk = sm.icnt;
            float scQ = sm.bc[0], scK = sm.bc[1];
            float q0 = 0.f, q1 = 0.f, k0 = 0.f, k1 = 0.f;
            #pragma unroll 4
            for (int j = 0; j < nk; j++){
                const float* row = qk_neurons + (size_t)sm.klist[j] * ND;
                float cq = sm.kc1[j] * scQ, ck = sm.kc2[j] * scK;
                float r0 = row[tid], r1 = row[tid + 256];
                q0 += cq * r0; q1 += cq * r1;
                k0 += ck * r0; k1 += ck * r1;
            }
            g_Q[(size_t)token * ND + tid] = q0; g_Q[(size_t)token * ND + tid + 256] = q1;
            g_K[(size_t)token * ND + tid] = k0; g_K[(size_t)token * ND + tid + 256] = k1;
        }
        __syncthreads();
    }

    // ================= V set (gate V) =================
    {
        float px = v_pos[token * 2 + 0], py = v_pos[token * 2 + 1];
        fill_cands(&sm, tid, px, py, pm0, pm1, pr0, pr1, cm_v);
        __syncthreads();
        cand_dots(&sm, tid, v_neurons);
        float tv_tau = tau_V[token];
        __syncthreads();
        for (int i = tid; i < NCAND; i += 256){
            float a = sm.act[i];
            float sc = (sm.cand[i] >= 0) ? a : -1e9f;
            sm.egA[i] = egf(sc, tv_tau);
        }
        __syncthreads();
        float mxV;
        float tvV = topk32(sm.egA, &sm, tid, &mxV);

        if (tid == 0) sm.icnt = 0;
        __syncthreads();
        float sV = 0.f, sVpd = 0.f;
        for (int r = 0; r < 2; r++){
            int i = r * 256 + tid;
            bool inb = (i < NCAND);
            float a = 0.f, wV = 0.f; int c = -1;
            bool keep = false;
            if (inb){
                c = sm.cand[i];
                a = sm.act[i];
                float eV = sm.egA[i];
                float kv = (eV >= tvV) ? eV : 0.f;
                if (c >= 0){
                    wV = kv;
                    sV += wV;
                    if (wV > 0.f){
                        float dx = px - npos_v[c * 2], dy = py - npos_v[c * 2 + 1];
                        sVpd += wV * (dx * dx + dy * dy);
                    }
                    keep = (wV != 0.f);
                }
            }
            unsigned bal = __ballot_sync(0xffffffffu, keep);
            int wlt = __popc(bal & ((1u << (tid & 31)) - 1u));
            if ((tid & 31) == 0) sm.wcnt[tid >> 5] = __popc(bal);
            __syncthreads();
            if (tid == 0){
                int base = sm.icnt;
                for (int w2 = 0; w2 < 8; w2++){ int t = sm.wcnt[w2]; sm.wcnt[w2] = base; base += t; }
                sm.icnt = base;
            }
            __syncthreads();
            if (keep){
                int p = sm.wcnt[tid >> 5] + wlt;
                sm.klist[p] = c;
                sm.kc1[p] = a * wV;
            }
            __syncthreads();
        }
        #pragma unroll
        for (int o = 16; o; o >>= 1){
            sV   += __shfl_xor_sync(0xffffffffu, sV, o);
            sVpd += __shfl_xor_sync(0xffffffffu, sVpd, o);
        }
        if ((tid & 31) == 0){ sm.redf[0][tid >> 5] = sV; sm.redf[2][tid >> 5] = sVpd; }
        __syncthreads();
        if (tid == 0){
            float a0 = 0.f, a2 = 0.f;
            for (int w2 = 0; w2 < 8; w2++){ a0 += sm.redf[0][w2]; a2 += sm.redf[2][w2]; }
            float scV = tanhf(mxV) / (a0 + 1e-8f);
            sm.bc[0] = scV;
            g_posbuf[NTOK + token] = scV * a2;
        }
        __syncthreads();
        {
            int nk = sm.icnt;
            float scV = sm.bc[0];
            float v0 = 0.f, v1 = 0.f;
            #pragma unroll 4
            for (int j = 0; j < nk; j++){
                const float* row = v_neurons + (size_t)sm.klist[j] * ND;
                float cv = sm.kc1[j] * scV;
                v0 += cv * row[tid]; v1 += cv * row[tid + 256];
            }
            g_V[(size_t)token * ND + tid] = v0; g_V[(size_t)token * ND + tid + 256] = v1;
        }
    }
}

// deterministic pos_loss reduction (fixed tree, no atomics)
__global__ void pos_reduce(float* out, int has_tail){
    __shared__ float red[8];
    int tid = threadIdx.x;
    float s = 0.f;
    for (int i = tid; i < NTOK * 2; i += 256) s += g_posbuf[i];
    #pragma unroll
    for (int o = 16; o; o >>= 1) s += __shfl_xor_sync(0xffffffffu, s, o);
    if ((tid & 31) == 0) red[tid >> 5] = s;
    __syncthreads();
    if (tid == 0){
        float t = 0.f;
        for (int w = 0; w < 8; w++) t += red[w];
        if (has_tail) out[(size_t)NTOK * ND] = t * (1.0f / (8.0f * 73728.0f));
    }
}

// causal flash attention, fp32, 64q x 32t tiles, 256 threads (16x16), 4x4 microtiles
__global__ __launch_bounds__(256)
void attn_kernel(){
    __shared__ float Qs[64][65];
    __shared__ float Ks[32][65];
    __shared__ float Vs[32][65];
    __shared__ float Ps[64][33];
    int tid = threadIdx.x;
    int qb = blockIdx.x & 15;
    int h  = (blockIdx.x >> 4) & 7;
    int b  = blockIdx.x >> 7;
    int q0 = qb * 64;
    const float* Qg = g_Q + (size_t)b * NS * ND + h * DHEAD;
    const float* Kg = g_K + (size_t)b * NS * ND + h * DHEAD;
    const float* Vg = g_V + (size_t)b * NS * ND + h * DHEAD;

    for (int i = tid; i < 64 * 64; i += 256){
        int r = i >> 6, c = i & 63;
        Qs[r][c] = Qg[(size_t)(q0 + r) * ND + c];
    }
    int tx = tid & 15, ty = tid >> 4;
    float acc[4][4];
    float m[4], l[4];
    #pragma unroll
    for (int qi = 0; qi < 4; qi++){
        m[qi] = -FLT_MAX; l[qi] = 0.f;
        #pragma unroll
        for (int di = 0; di < 4; di++) acc[qi][di] = 0.f;
    }
    int ntile = (qb + 1) * 2;
    for (int kt = 0; kt < ntile; kt++){
        int t0 = kt * 32;
        __syncthreads();
        for (int i = tid; i < 32 * 64; i += 256){
            int r = i >> 6, c = i & 63;
            Ks[r][c] = Kg[(size_t)(t0 + r) * ND + c];
            Vs[r][c] = Vg[(size_t)(t0 + r) * ND + c];
        }
        __syncthreads();
        float sf[4][2] = {{0.f,0.f},{0.f,0.f},{0.f,0.f},{0.f,0.f}};
        #pragma unroll 4
        for (int d = 0; d < 64; d++){
            float kf0 = Ks[tx * 2][d], kf1 = Ks[tx * 2 + 1][d];
            #pragma unroll
            for (int qi = 0; qi < 4; qi++){
                float qv = Qs[ty * 4 + qi][d];
                sf[qi][0] += qv * kf0;
                sf[qi][1] += qv * kf1;
            }
        }
        const float scl = 0.125f;
        #pragma unroll
        for (int qi = 0; qi < 4; qi++){
            int qg = q0 + ty * 4 + qi;
            float v0 = (t0 + tx * 2     <= qg) ? sf[qi][0] * scl : -FLT_MAX;
            float v1 = (t0 + tx * 2 + 1 <= qg) ? sf[qi][1] * scl : -FLT_MAX;
            float rm = fmaxf(v0, v1);
            #pragma unroll
            for (int o = 1; o < 16; o <<= 1) rm = fmaxf(rm, __shfl_xor_sync(0xffffffffu, rm, o));
            float mn = fmaxf(m[qi], rm);
            float corr = expf(m[qi] - mn);
            float p0 = expf(v0 - mn), p1 = expf(v1 - mn);
            float rs = p0 + p1;
            #pragma unroll
            for (int o = 1; o < 16; o <<= 1) rs += __shfl_xor_sync(0xffffffffu, rs, o);
            l[qi] = l[qi] * corr + rs;
            #pragma unroll
            for (int di = 0; di < 4; di++) acc[qi][di] *= corr;
            m[qi] = mn;
            Ps[ty * 4 + qi][tx * 2] = p0;
            Ps[ty * 4 + qi][tx * 2 + 1] = p1;
        }
        __syncthreads();
        #pragma unroll 4
        for (int t = 0; t < 32; t++){
            float vf0 = Vs[t][tx * 4], vf1 = Vs[t][tx * 4 + 1];
            float vf2 = Vs[t][tx * 4 + 2], vf3 = Vs[t][tx * 4 + 3];
            #pragma unroll
            for (int qi = 0; qi < 4; qi++){
                float p = Ps[ty * 4 + qi][t];
                acc[qi][0] += p * vf0; acc[qi][1] += p * vf1;
                acc[qi][2] += p * vf2; acc[qi][3] += p * vf3;
            }
        }
    }
    float* Og = g_AO + (size_t)b * NS * ND + h * DHEAD;
    #pragma unroll
    for (int qi = 0; qi < 4; qi++){
        float inv = 1.0f / l[qi];
        #pragma unroll
        for (int di = 0; di < 4; di++)
            Og[(size_t)(q0 + ty * 4 + qi) * ND + tx * 4 + di] = acc[qi][di] * inv;
    }
}

// final projection: out = g_AO[2048x512] @ expand_O[512x512]
__global__ __launch_bounds__(256)
void out_gemm(const float* __restrict__ Bmat, float* __restrict__ out){
    __shared__ float As[64][33];
    __shared__ float Bs[32][65];
    int tid = threadIdx.x;
    int m0 = blockIdx.y * 64, n0 = blockIdx.x * 64;
    int tx = tid & 15, ty = tid >> 4;
    float acc[4][4];
    #pragma unroll
    for (int i = 0; i < 4; i++)
        #pragma unroll
        for (int j = 0; j < 4; j++) acc[i][j] = 0.f;
    for (int k0 = 0; k0 < ND; k0 += 32){
        __syncthreads();
        for (int i = tid; i < 64 * 32; i += 256){
            int r = i >> 5, c = i & 31;
            As[r][c] = g_AO[(size_t)(m0 + r) * ND + k0 + c];
        }
        for (int i = tid; i < 32 * 64; i += 256){
            int r = i >> 6, c = i & 63;
            Bs[r][c] = Bmat[(size_t)(k0 + r) * ND + n0 + c];
        }
        __syncthreads();
        #pragma unroll 8
        for (int k = 0; k < 32; k++){
            float a[4], bv[4];
            #pragma unroll
            for (int qi = 0; qi < 4; qi++) a[qi] = As[ty * 4 + qi][k];
            #pragma unroll
            for (int ni = 0; ni < 4; ni++) bv[ni] = Bs[k][tx * 4 + ni];
            #pragma unroll
            for (int qi = 0; qi < 4; qi++)
                #pragma unroll
                for (int ni = 0; ni < 4; ni++) acc[qi][ni] += a[qi] * bv[ni];
        }
    }
    #pragma unroll
    for (int qi = 0; qi < 4; qi++)
        #pragma unroll
        for (int ni = 0; ni < 4; ni++)
            out[(size_t)(m0 + ty * 4 + qi) * ND + n0 + tx * 4 + ni] = acc[qi][ni];
}

extern "C" void kernel_launch(void* const* d_in, const int* in_sizes, int n_in,
                              void* d_out, int out_size){
    const float* x          = (const float*)d_in[0];
    const float* qk_pos     = (const float*)d_in[1];
    const float* v_pos      = (const float*)d_in[2];
    const float* tau_Q      = (const float*)d_in[3];
    const float* tau_K      = (const float*)d_in[4];
    const float* tau_V      = (const float*)d_in[5];
    const float* qk_neurons = (const float*)d_in[6];
    const float* v_neurons  = (const float*)d_in[7];
    const float* npos_qk    = (const float*)d_in[8];
    const float* npos_v     = (const float*)d_in[9];
    const int*   cm_qk      = (const int*)d_in[10];
    const int*   cm_v       = (const int*)d_in[11];
    const float* pos_min    = (const float*)d_in[12];
    const float* pos_range  = (const float*)d_in[13];
    const float* expand_O   = (const float*)d_in[14];
    float* out = (float*)d_out;

    token_kernel<<<NTOK, 256>>>(x, qk_pos, v_pos, tau_Q, tau_K, tau_V,
                                qk_neurons, v_neurons, npos_qk, npos_v,
                                cm_qk, cm_v, pos_min, pos_range);
    int has_tail = (out_size > NTOK * ND) ? 1 : 0;
    pos_reduce<<<1, 256>>>(out, has_tail);
    attn_kernel<<<NB * NHEAD * (NS / 64), 256>>>();
    dim3 g(ND / 64, NTOK / 64);
    out_gemm<<<g, 256>>>(expand_O, out);
}